// round 2
// baseline (speedup 1.0000x reference)
#include <cuda_runtime.h>
#include <math.h>

// Problem constants
#define BSZ   512
#define DD    64
#define DE    65
#define JK    4225      // 65*65
#define NOUT  256
#define KTOT  274625    // 65^3
#define NSPLIT 13
#define ISPL   5        // 13*5 = 65 i-values

// Scratch (static device allocation only — harness forbids cudaMalloc)
__device__ float g_oe[3 * BSZ * DE];          // o1e/o2e/o3e with appended 1.0, [br][b][65]
__device__ float g_P[BSZ * JK];               // P[b][jk] = o2e[b][j]*o3e[b][k]
__device__ float g_part[NSPLIT * BSZ * NOUT]; // split-K partials [z][b][o]

struct Ptrs { const float* p[25]; };

__device__ __forceinline__ unsigned long long dup2(float x) {
    unsigned long long r;
    asm("mov.b64 %0, {%1, %1};" : "=l"(r) : "r"(__float_as_uint(x)));
    return r;
}
__device__ __forceinline__ void fma2(unsigned long long& acc, unsigned long long a, unsigned long long b) {
    asm("fma.rn.f32x2 %0, %1, %2, %0;" : "+l"(acc) : "l"(a), "l"(b));
}

// ---------------------------------------------------------------------------
// Kernel 1: three gated branches -> o1e/o2e/o3e [512][65] (last col = 1.0)
// Grid 32 blocks x 16 batch each, 256 threads (thread = (o, bgroup))
// ---------------------------------------------------------------------------
__global__ __launch_bounds__(256) void k_branches(Ptrs P) {
    __shared__ float vs[3][16][DD];
    __shared__ float gs[16][DD];
    int b0 = blockIdx.x * 16;
    int t = threadIdx.x;

    for (int e = t; e < 16 * DD; e += 256) {
        int bb = e >> 6, m = e & 63;
        vs[0][bb][m] = P.p[0][(b0 + bb) * DD + m];
        vs[1][bb][m] = P.p[1][(b0 + bb) * DD + m];
        vs[2][bb][m] = P.p[2][(b0 + bb) * DD + m];
    }
    __syncthreads();

    int o = t & 63, bg = t >> 6;  // 64 o's x 4 bgroups, each bgroup owns 4 batch rows
    for (int br = 0; br < 3; ++br) {
        const float* hw = P.p[3 + br * 6];
        const float* hb = P.p[4 + br * 6];
        const float* zw = P.p[5 + br * 6];
        const float* zb = P.p[6 + br * 6];
        const float* ow = P.p[7 + br * 6];
        const float* ob = P.p[8 + br * 6];
        int hv = br;                 // h1<-vec1, h2<-vec2, h3<-vec3
        int x1 = (br == 1) ? 1 : 0;  // z1:(v1,v3)  z2:(v2,v3)  z3:(v1,v3)

        float hacc[4], zacc[4];
        #pragma unroll
        for (int q = 0; q < 4; q++) { hacc[q] = hb[o]; zacc[q] = zb[o]; }

        const float* hwr = hw + o * DD;
        #pragma unroll 8
        for (int m = 0; m < DD; m++) {
            float w = hwr[m];
            #pragma unroll
            for (int q = 0; q < 4; q++) hacc[q] += w * vs[hv][bg * 4 + q][m];
        }

        for (int i = 0; i < DD; i++) {
            float s[4] = {0.f, 0.f, 0.f, 0.f};
            const float* zr = zw + o * DD * DD + i * DD;
            #pragma unroll 8
            for (int j = 0; j < DD; j++) {
                float w = zr[j];
                #pragma unroll
                for (int q = 0; q < 4; q++) s[q] += w * vs[2][bg * 4 + q][j];
            }
            #pragma unroll
            for (int q = 0; q < 4; q++) zacc[q] += vs[x1][bg * 4 + q][i] * s[q];
        }

        #pragma unroll
        for (int q = 0; q < 4; q++) {
            float h = fmaxf(hacc[q], 0.f);
            float sg = 1.f / (1.f + expf(-zacc[q]));
            gs[bg * 4 + q][o] = h * sg;
        }
        __syncthreads();

        float oacc[4];
        #pragma unroll
        for (int q = 0; q < 4; q++) oacc[q] = ob[o];
        const float* owr = ow + o * DD;
        #pragma unroll 8
        for (int m = 0; m < DD; m++) {
            float w = owr[m];
            #pragma unroll
            for (int q = 0; q < 4; q++) oacc[q] += w * gs[bg * 4 + q][m];
        }
        #pragma unroll
        for (int q = 0; q < 4; q++) {
            g_oe[((long long)br * BSZ + b0 + bg * 4 + q) * DE + o] = fmaxf(oacc[q], 0.f);
            if (o == 0) g_oe[((long long)br * BSZ + b0 + bg * 4 + q) * DE + DD] = 1.f;
        }
        __syncthreads();
    }
}

// ---------------------------------------------------------------------------
// Kernel 2: P[b][j*65+k] = o2e[b][j] * o3e[b][k]
// ---------------------------------------------------------------------------
__global__ __launch_bounds__(256) void k_pair() {
    int b = blockIdx.x, t = threadIdx.x;
    __shared__ float s2[DE], s3[DE];
    if (t < DE)           s2[t]      = g_oe[(1 * BSZ + b) * DE + t];
    else if (t < 2 * DE)  s3[t - DE] = g_oe[(2 * BSZ + b) * DE + (t - DE)];
    __syncthreads();
    for (int e = t; e < JK; e += 256) {
        int j = e / DE, k = e - j * DE;
        g_P[b * JK + e] = s2[j] * s3[k];
    }
}

// ---------------------------------------------------------------------------
// Kernel 3: big GEMM  C[o, b] = sum_{i,jk} W[o, i*4225+jk] * o1e[b,i] * P[b,jk]
// Split-K over i (13 splits of 5). Tile 64(o) x 64(b). fp32x2 FFMA2.
// Grid (8 btiles, 4 otiles, 13 splits), 256 threads, each thread 4x4 outputs.
// ---------------------------------------------------------------------------
__global__ __launch_bounds__(256) void k_gemm(const float* __restrict__ W) {
    __shared__ __align__(16) float As[DE][68];  // [kk][m]  (transposed for float4 LDS)
    __shared__ __align__(16) float Bs[DE][68];  // [kk][n]
    __shared__ float o1t[64][ISPL];

    int b0 = blockIdx.x * 64, o0 = blockIdx.y * 64, z = blockIdx.z;
    int i0 = z * ISPL;
    int t = threadIdx.x;

    for (int e = t; e < 64 * ISPL; e += 256) {
        int n = e / ISPL, ii = e - n * ISPL;
        o1t[n][ii] = g_oe[(0 * BSZ + b0 + n) * DE + i0 + ii];
    }

    unsigned long long acc[4][2];
    #pragma unroll
    for (int a = 0; a < 4; a++)
        #pragma unroll
        for (int p = 0; p < 2; p++) acc[a][p] = 0ull;

    int m0 = (t >> 4) << 2;   // 16 m-groups of 4
    int n0 = (t & 15) << 2;   // 16 n-groups of 4

    for (int ii = 0; ii < ISPL; ++ii) {
        long long kbase = (long long)(i0 + ii) * JK;
        for (int c = 0; c < 65; ++c) {
            __syncthreads();
            for (int e = t; e < 64 * 65; e += 256) {
                int r = e / 65, kk = e - r * 65;
                As[kk][r] = W[(long long)(o0 + r) * (long long)KTOT + kbase + c * 65 + kk];
                Bs[kk][r] = o1t[r][ii] * g_P[(b0 + r) * JK + c * 65 + kk];
            }
            __syncthreads();
            #pragma unroll 13
            for (int kk = 0; kk < 65; ++kk) {
                float4 a4 = *(const float4*)&As[kk][m0];
                ulonglong2 bb = *(const ulonglong2*)&Bs[kk][n0];
                unsigned long long a0 = dup2(a4.x), a1 = dup2(a4.y),
                                   a2 = dup2(a4.z), a3 = dup2(a4.w);
                fma2(acc[0][0], a0, bb.x); fma2(acc[0][1], a0, bb.y);
                fma2(acc[1][0], a1, bb.x); fma2(acc[1][1], a1, bb.y);
                fma2(acc[2][0], a2, bb.x); fma2(acc[2][1], a2, bb.y);
                fma2(acc[3][0], a3, bb.x); fma2(acc[3][1], a3, bb.y);
            }
        }
    }

    #pragma unroll
    for (int mi = 0; mi < 4; ++mi)
        #pragma unroll
        for (int p = 0; p < 2; ++p) {
            unsigned long long v = acc[mi][p];
            float lo = __uint_as_float((unsigned)v);
            float hi = __uint_as_float((unsigned)(v >> 32));
            g_part[((z * BSZ) + b0 + n0 + 2 * p)     * NOUT + o0 + m0 + mi] = lo;
            g_part[((z * BSZ) + b0 + n0 + 2 * p + 1) * NOUT + o0 + m0 + mi] = hi;
        }
}

// ---------------------------------------------------------------------------
// Kernel 4: reduce split-K partials + enc1 bias/relu + skip concat + enc2
// Grid 32 blocks x 16 batch, 256 threads (thread = output neuron n2)
// ---------------------------------------------------------------------------
__global__ __launch_bounds__(256) void k_epi(const float* __restrict__ e1b,
                                             const float* __restrict__ e2w,
                                             const float* __restrict__ e2b,
                                             float* __restrict__ out) {
    __shared__ float E[16][452];
    int b0 = blockIdx.x * 16, t = threadIdx.x;

    // enc1 output (m = t), coalesced partial reads
    for (int bb = 0; bb < 16; ++bb) {
        float s = e1b[t];
        #pragma unroll
        for (int z = 0; z < NSPLIT; ++z) s += g_part[((z * BSZ) + b0 + bb) * NOUT + t];
        E[bb][t] = fmaxf(s, 0.f);
    }
    // skip connections: [o1e | o2e | o3e] (ones already embedded)
    for (int e = t; e < 16 * 195; e += 256) {
        int bb = e / 195, q = e - bb * 195;
        E[bb][256 + q] = g_oe[((q / 65) * BSZ + b0 + bb) * DE + (q % 65)];
    }
    __syncthreads();

    float acc[16];
    #pragma unroll
    for (int bb = 0; bb < 16; bb++) acc[bb] = 0.f;
    const float* wr = e2w + t * 451;
    for (int m = 0; m < 451; m++) {
        float w = wr[m];
        #pragma unroll
        for (int bb = 0; bb < 16; bb++) acc[bb] += w * E[bb][m];
    }
    float bias = e2b[t];
    #pragma unroll
    for (int bb = 0; bb < 16; bb++)
        out[(b0 + bb) * NOUT + t] = fmaxf(acc[bb] + bias, 0.f);
}

// ---------------------------------------------------------------------------
extern "C" void kernel_launch(void* const* d_in, const int* in_sizes, int n_in,
                              void* d_out, int out_size) {
    Ptrs P;
    for (int i = 0; i < 25; i++) P.p[i] = (const float*)d_in[i];

    k_branches<<<32, 256>>>(P);
    k_pair<<<512, 256>>>();
    dim3 g(8, 4, 13);
    k_gemm<<<g, 256>>>((const float*)d_in[21]);
    k_epi<<<32, 256>>>((const float*)d_in[22], (const float*)d_in[23],
                       (const float*)d_in[24], (float*)d_out);
}

// round 4
// speedup vs baseline: 1.6641x; 1.6641x over previous
#include <cuda_runtime.h>
#include <cuda_bf16.h>
#include <math.h>
#include <stdint.h>

// Problem constants
#define BSZ   512
#define DD    64
#define DE    65
#define JK    4225      // 65*65
#define NOUT  256
#define KTOT  274625    // 65^3
#define ZSPLIT 18
#define NCH_TOT 8583    // ceil(274625/32)
#define CH_PER 477      // ceil(8583/18)

// Scratch (static device arrays only)
__device__ float g_oe[3 * BSZ * DE];            // o1e/o2e/o3e with appended 1.0
__device__ float g_P[BSZ * JK];                 // P[b][jk] = o2e[b][j]*o3e[b][k]
__device__ float g_part[ZSPLIT * BSZ * NOUT];   // split-K partials [z][b][o]
__device__ float g_E[BSZ * 456];                // enc2 input [relu(enc1)|skips|pad]

struct Ptrs { const float* p[25]; };

__device__ __forceinline__ unsigned long long dup2(float x) {
    unsigned long long r;
    asm("mov.b64 %0, {%1, %1};" : "=l"(r) : "r"(__float_as_uint(x)));
    return r;
}
__device__ __forceinline__ void fma2(unsigned long long& acc, unsigned long long a, unsigned long long b) {
    asm("fma.rn.f32x2 %0, %1, %2, %0;" : "+l"(acc) : "l"(a), "l"(b));
}

__device__ __forceinline__ void mma_bf16(float* d, const uint32_t* a, const uint32_t* b) {
    asm volatile("mma.sync.aligned.m16n8k16.row.col.f32.bf16.bf16.f32 "
        "{%0,%1,%2,%3}, {%4,%5,%6,%7}, {%8,%9}, {%0,%1,%2,%3};"
        : "+f"(d[0]), "+f"(d[1]), "+f"(d[2]), "+f"(d[3])
        : "r"(a[0]), "r"(a[1]), "r"(a[2]), "r"(a[3]), "r"(b[0]), "r"(b[1]));
}

// ---------------------------------------------------------------------------
// Kernel 1: three gated branches -> o1e/o2e/o3e [512][65] (last col = 1.0)
// ---------------------------------------------------------------------------
__global__ __launch_bounds__(256) void k_branches(Ptrs P) {
    __shared__ float vs[3][16][DD];
    __shared__ float gs[16][DD];
    int b0 = blockIdx.x * 16;
    int t = threadIdx.x;

    for (int e = t; e < 16 * DD; e += 256) {
        int bb = e >> 6, m = e & 63;
        vs[0][bb][m] = P.p[0][(b0 + bb) * DD + m];
        vs[1][bb][m] = P.p[1][(b0 + bb) * DD + m];
        vs[2][bb][m] = P.p[2][(b0 + bb) * DD + m];
    }
    __syncthreads();

    int o = t & 63, bg = t >> 6;
    for (int br = 0; br < 3; ++br) {
        const float* hw = P.p[3 + br * 6];
        const float* hb = P.p[4 + br * 6];
        const float* zw = P.p[5 + br * 6];
        const float* zb = P.p[6 + br * 6];
        const float* ow = P.p[7 + br * 6];
        const float* ob = P.p[8 + br * 6];
        int hv = br;
        int x1 = (br == 1) ? 1 : 0;

        float hacc[4], zacc[4];
        #pragma unroll
        for (int q = 0; q < 4; q++) { hacc[q] = hb[o]; zacc[q] = zb[o]; }

        const float* hwr = hw + o * DD;
        #pragma unroll 8
        for (int m = 0; m < DD; m++) {
            float w = hwr[m];
            #pragma unroll
            for (int q = 0; q < 4; q++) hacc[q] += w * vs[hv][bg * 4 + q][m];
        }

        for (int i = 0; i < DD; i++) {
            float s[4] = {0.f, 0.f, 0.f, 0.f};
            const float* zr = zw + o * DD * DD + i * DD;
            #pragma unroll 8
            for (int j = 0; j < DD; j++) {
                float w = zr[j];
                #pragma unroll
                for (int q = 0; q < 4; q++) s[q] += w * vs[2][bg * 4 + q][j];
            }
            #pragma unroll
            for (int q = 0; q < 4; q++) zacc[q] += vs[x1][bg * 4 + q][i] * s[q];
        }

        #pragma unroll
        for (int q = 0; q < 4; q++) {
            float h = fmaxf(hacc[q], 0.f);
            float sg = 1.f / (1.f + expf(-zacc[q]));
            gs[bg * 4 + q][o] = h * sg;
        }
        __syncthreads();

        float oacc[4];
        #pragma unroll
        for (int q = 0; q < 4; q++) oacc[q] = ob[o];
        const float* owr = ow + o * DD;
        #pragma unroll 8
        for (int m = 0; m < DD; m++) {
            float w = owr[m];
            #pragma unroll
            for (int q = 0; q < 4; q++) oacc[q] += w * gs[bg * 4 + q][m];
        }
        #pragma unroll
        for (int q = 0; q < 4; q++) {
            g_oe[((long long)br * BSZ + b0 + bg * 4 + q) * DE + o] = fmaxf(oacc[q], 0.f);
            if (o == 0) g_oe[((long long)br * BSZ + b0 + bg * 4 + q) * DE + DD] = 1.f;
        }
        __syncthreads();
    }
}

// ---------------------------------------------------------------------------
// Kernel 2: P[b][j*65+k] = o2e[b][j] * o3e[b][k]
// ---------------------------------------------------------------------------
__global__ __launch_bounds__(256) void k_pair() {
    int b = blockIdx.x, t = threadIdx.x;
    __shared__ float s2[DE], s3[DE];
    if (t < DE)           s2[t]      = g_oe[(1 * BSZ + b) * DE + t];
    else if (t < 2 * DE)  s3[t - DE] = g_oe[(2 * BSZ + b) * DE + (t - DE)];
    __syncthreads();
    for (int e = t; e < JK; e += 256) {
        int j = e / DE, k = e - j * DE;
        g_P[b * JK + e] = s2[j] * s3[k];
    }
}

// ---------------------------------------------------------------------------
// Kernel 3: big GEMM via mma.sync bf16 3-pass (base-PTX tensor path).
// C[o 256, b 512] = sum_kb W[o,kb] * Bmat[kb,b], Bmat = o1e[b,i]*P[b,jk].
// CTA tile 128(o) x 128(b), chunk = 32 k, grid (4 btiles, 2 otiles, 18 splits).
// ---------------------------------------------------------------------------
#define SROW     80                 // bytes per smem row (40 bf16, conflict-free pad)
#define O1_BYTES (128 * 66 * 4)     // 33792
#define STAGE_SZ 40960              // 4 planes * 128 rows * 80 B
#define AH_OFF   0
#define AL_OFF   10240
#define BH_OFF   20480
#define BL_OFF   30720
#define SMEM_GEMM (O1_BYTES + 2 * STAGE_SZ)

__global__ __launch_bounds__(256, 1) void k_gemm_mma(const float* __restrict__ W) {
    extern __shared__ char smem[];
    float* o1s = (float*)smem;                       // [128][66]
    const int t = threadIdx.x, w = t >> 5, lane = t & 31;
    const int gid = lane >> 2, tig = lane & 3;
    const int warp_m = w >> 2, warp_n = w & 3;
    const int b0 = blockIdx.x * 128, o0 = blockIdx.y * 128, z = blockIdx.z;

    // cache o1e for this CTA's b-range
    for (int e = t; e < 128 * DE; e += 256) {
        int bl = e / DE, ii = e - bl * DE;
        o1s[bl * 66 + ii] = g_oe[(b0 + bl) * DE + ii];
    }
    __syncthreads();

    const int c0 = z * CH_PER;
    const int nch = min(c0 + CH_PER, NCH_TOT) - c0;

    float acc[4][4][4];
    #pragma unroll
    for (int mt = 0; mt < 4; mt++)
        #pragma unroll
        for (int nt = 0; nt < 4; nt++)
            #pragma unroll
            for (int q = 0; q < 4; q++) acc[mt][nt][q] = 0.f;

    float aR[16], bR[16];

    // prefetch chunk c0
    {
        int kb = c0 * 32 + lane;
        bool ok = kb < KTOT;
        int kk = ok ? kb : 0;
        int i = kk / JK, jk = kk - i * JK;
        const float* wp = W + (size_t)(o0 + w * 16) * KTOT + kk;
        const float* pp = g_P + (size_t)(b0 + w * 16) * JK + jk;
        #pragma unroll
        for (int r = 0; r < 16; r++) {
            aR[r] = ok ? __ldg(wp + (size_t)r * KTOT) : 0.f;
            bR[r] = ok ? __ldg(pp + (size_t)r * JK) : 0.f;
        }
    }

    for (int ci = 0; ci < nch; ++ci) {
        const int s = ci & 1;
        char* st = smem + O1_BYTES + s * STAGE_SZ;

        // store prefetched chunk to smem as bf16 hi/lo planes
        {
            int kb = (c0 + ci) * 32 + lane;
            int kk = (kb < KTOT) ? kb : 0;
            int i = kk / JK;
            uint32_t off = (uint32_t)(w * 16) * SROW + lane * 2;
            #pragma unroll
            for (int r = 0; r < 16; r++) {
                float v = aR[r];
                __nv_bfloat16 h = __float2bfloat16(v);
                __nv_bfloat16 l = __float2bfloat16(v - __bfloat162float(h));
                *(__nv_bfloat16*)(st + AH_OFF + off + r * SROW) = h;
                *(__nv_bfloat16*)(st + AL_OFF + off + r * SROW) = l;
                float u = bR[r] * o1s[(w * 16 + r) * 66 + i];
                __nv_bfloat16 h2 = __float2bfloat16(u);
                __nv_bfloat16 l2 = __float2bfloat16(u - __bfloat162float(h2));
                *(__nv_bfloat16*)(st + BH_OFF + off + r * SROW) = h2;
                *(__nv_bfloat16*)(st + BL_OFF + off + r * SROW) = l2;
            }
        }
        __syncthreads();

        // prefetch next chunk (hidden under mma below)
        if (ci + 1 < nch) {
            int kb = (c0 + ci + 1) * 32 + lane;
            bool ok = kb < KTOT;
            int kk = ok ? kb : 0;
            int i = kk / JK, jk = kk - i * JK;
            const float* wp = W + (size_t)(o0 + w * 16) * KTOT + kk;
            const float* pp = g_P + (size_t)(b0 + w * 16) * JK + jk;
            #pragma unroll
            for (int r = 0; r < 16; r++) {
                aR[r] = ok ? __ldg(wp + (size_t)r * KTOT) : 0.f;
                bR[r] = ok ? __ldg(pp + (size_t)r * JK) : 0.f;
            }
        }

        // compute on stage s
        {
            const char* sc = smem + O1_BYTES + s * STAGE_SZ;
            #pragma unroll
            for (int kh = 0; kh < 2; ++kh) {
                uint32_t ah[4][4], al[4][4], bh[4][2], bl[4][2];
                #pragma unroll
                for (int mt = 0; mt < 4; mt++) {
                    uint32_t r0 = (uint32_t)(warp_m * 64 + mt * 16 + gid) * SROW + tig * 4 + kh * 32;
                    ah[mt][0] = *(const uint32_t*)(sc + AH_OFF + r0);
                    ah[mt][1] = *(const uint32_t*)(sc + AH_OFF + r0 + 8 * SROW);
                    ah[mt][2] = *(const uint32_t*)(sc + AH_OFF + r0 + 16);
                    ah[mt][3] = *(const uint32_t*)(sc + AH_OFF + r0 + 8 * SROW + 16);
                    al[mt][0] = *(const uint32_t*)(sc + AL_OFF + r0);
                    al[mt][1] = *(const uint32_t*)(sc + AL_OFF + r0 + 8 * SROW);
                    al[mt][2] = *(const uint32_t*)(sc + AL_OFF + r0 + 16);
                    al[mt][3] = *(const uint32_t*)(sc + AL_OFF + r0 + 8 * SROW + 16);
                }
                #pragma unroll
                for (int nt = 0; nt < 4; nt++) {
                    uint32_t r0 = (uint32_t)(warp_n * 32 + nt * 8 + gid) * SROW + tig * 4 + kh * 32;
                    bh[nt][0] = *(const uint32_t*)(sc + BH_OFF + r0);
                    bh[nt][1] = *(const uint32_t*)(sc + BH_OFF + r0 + 16);
                    bl[nt][0] = *(const uint32_t*)(sc + BL_OFF + r0);
                    bl[nt][1] = *(const uint32_t*)(sc + BL_OFF + r0 + 16);
                }
                #pragma unroll
                for (int mt = 0; mt < 4; mt++)
                    #pragma unroll
                    for (int nt = 0; nt < 4; nt++)
                        mma_bf16(acc[mt][nt], ah[mt], bh[nt]);
                #pragma unroll
                for (int mt = 0; mt < 4; mt++)
                    #pragma unroll
                    for (int nt = 0; nt < 4; nt++)
                        mma_bf16(acc[mt][nt], al[mt], bh[nt]);
                #pragma unroll
                for (int mt = 0; mt < 4; mt++)
                    #pragma unroll
                    for (int nt = 0; nt < 4; nt++)
                        mma_bf16(acc[mt][nt], ah[mt], bl[nt]);
            }
        }
    }

    // epilogue: acc -> g_part[z][b][o]
    float* gp = g_part + (size_t)z * BSZ * NOUT;
    #pragma unroll
    for (int mt = 0; mt < 4; mt++) {
        int o = o0 + warp_m * 64 + mt * 16 + gid;
        #pragma unroll
        for (int nt = 0; nt < 4; nt++) {
            int b = b0 + warp_n * 32 + nt * 8 + tig * 2;
            gp[(size_t)b * NOUT + o]           = acc[mt][nt][0];
            gp[(size_t)(b + 1) * NOUT + o]     = acc[mt][nt][1];
            gp[(size_t)b * NOUT + o + 8]       = acc[mt][nt][2];
            gp[(size_t)(b + 1) * NOUT + o + 8] = acc[mt][nt][3];
        }
    }
}

// ---------------------------------------------------------------------------
// Kernel 4: reduce split-K partials + enc1 bias/relu + build enc2 input
// ---------------------------------------------------------------------------
__global__ __launch_bounds__(256) void k_reduce(const float* __restrict__ e1b) {
    int b = blockIdx.x, t = threadIdx.x;
    float s = e1b[t];
    #pragma unroll 6
    for (int zz = 0; zz < ZSPLIT; ++zz)
        s += g_part[((size_t)zz * BSZ + b) * NOUT + t];
    g_E[b * 456 + t] = fmaxf(s, 0.f);
    if (t < 195)
        g_E[b * 456 + 256 + t] = g_oe[((t / 65) * BSZ + b) * DE + (t % 65)];
    else if (t < 200)
        g_E[b * 456 + 451 + (t - 195)] = 0.f;
}

// ---------------------------------------------------------------------------
// Kernel 5: enc2 tiled GEMM: out[b,n] = relu(E[b,:451] . e2w[n,:451] + e2b[n])
// ---------------------------------------------------------------------------
__global__ __launch_bounds__(256) void k_enc2(const float* __restrict__ e2w,
                                              const float* __restrict__ e2b,
                                              float* __restrict__ out) {
    __shared__ __align__(16) float As[64][68];
    __shared__ __align__(16) float Bs[64][68];
    int b0 = blockIdx.x * 64, n0 = blockIdx.y * 64;
    int t = threadIdx.x;
    int m0 = (t >> 4) << 2, q0 = (t & 15) << 2;

    unsigned long long acc[4][2];
    #pragma unroll
    for (int a = 0; a < 4; a++)
        #pragma unroll
        for (int p = 0; p < 2; p++) acc[a][p] = 0ull;

    for (int kc = 0; kc < 512; kc += 64) {
        __syncthreads();
        for (int e = t; e < 64 * 64; e += 256) {
            int r = e >> 6, kk = e & 63;
            int k = kc + kk;
            As[kk][r] = (k < 451) ? e2w[(n0 + r) * 451 + k] : 0.f;
            Bs[kk][r] = (k < 451) ? g_E[(b0 + r) * 456 + k] : 0.f;
        }
        __syncthreads();
        #pragma unroll 16
        for (int kk = 0; kk < 64; ++kk) {
            float4 a4 = *(const float4*)&As[kk][m0];
            ulonglong2 bb = *(const ulonglong2*)&Bs[kk][q0];
            unsigned long long a0 = dup2(a4.x), a1 = dup2(a4.y),
                               a2 = dup2(a4.z), a3 = dup2(a4.w);
            fma2(acc[0][0], a0, bb.x); fma2(acc[0][1], a0, bb.y);
            fma2(acc[1][0], a1, bb.x); fma2(acc[1][1], a1, bb.y);
            fma2(acc[2][0], a2, bb.x); fma2(acc[2][1], a2, bb.y);
            fma2(acc[3][0], a3, bb.x); fma2(acc[3][1], a3, bb.y);
        }
    }

    #pragma unroll
    for (int mi = 0; mi < 4; ++mi) {
        int n = n0 + m0 + mi;
        float bias = e2b[n];
        #pragma unroll
        for (int p = 0; p < 2; ++p) {
            unsigned long long v = acc[mi][p];
            float lo = __uint_as_float((unsigned)v);
            float hi = __uint_as_float((unsigned)(v >> 32));
            out[(b0 + q0 + 2 * p)     * NOUT + n] = fmaxf(lo + bias, 0.f);
            out[(b0 + q0 + 2 * p + 1) * NOUT + n] = fmaxf(hi + bias, 0.f);
        }
    }
}

// ---------------------------------------------------------------------------
extern "C" void kernel_launch(void* const* d_in, const int* in_sizes, int n_in,
                              void* d_out, int out_size) {
    Ptrs P;
    for (int i = 0; i < 25; i++) P.p[i] = (const float*)d_in[i];

    cudaFuncSetAttribute(k_gemm_mma, cudaFuncAttributeMaxDynamicSharedMemorySize, SMEM_GEMM);

    k_branches<<<32, 256>>>(P);
    k_pair<<<512, 256>>>();
    k_gemm_mma<<<dim3(4, 2, ZSPLIT), 256, SMEM_GEMM>>>((const float*)d_in[21]);
    k_reduce<<<512, 256>>>((const float*)d_in[22]);
    k_enc2<<<dim3(8, 4), 256>>>((const float*)d_in[23], (const float*)d_in[24], (float*)d_out);
}